// round 15
// baseline (speedup 1.0000x reference)
#include <cuda_runtime.h>
#include <cstdint>

#define MLEN  16
#define DDIM  128
#define LNUM  26
#define BPB   64      // words per block
#define NTHR  256     // 8 warps: 4 row-groups x 2 K-halves
#define GRID  256
#define XSTR  136     // padded floats per X row
#define NBUF  2
#define PSTR  20      // floats per partial slot (bank-conflict-free)

// ---- smem layout (float indices) ----
#define XS_F    (BPB * XSTR)                 // 8704 per buffer
#define XOFF(b) ((b) * XS_F)
#define BPOFF   (NBUF * XS_F)                // 17408: Bp 1024 uint2 = 2048 floats
#define PSOFF   (BPOFF + 2048)               // 19456: partials 128 slots x 20 = 2560
#define TSOFF   (PSOFF + 128 * PSTR)         // 22016: raw T 676
#define YSOFF   (TSOFF + LNUM * LNUM)        // 22692: Y labels 64*16
#define REDOFF  (YSOFF + BPB * MLEN)         // 23716
#define FLGOFF  (REDOFF + 4)
#define SMEM_F  (FLGOFF + 4)
#define SMEM_BYTES (SMEM_F * 4)              // ~92.7 KB -> 2 blocks/SM (16 warps)

__device__ float g_partials[GRID];
__device__ unsigned int g_count;

static __device__ __forceinline__ void cp16(uint32_t dst, const void* src){
    asm volatile("cp.async.cg.shared.global [%0], [%1], 16;" :: "r"(dst), "l"(src));
}
static __device__ __forceinline__ void pref_l2(const void* p){
    asm volatile("prefetch.global.L2 [%0];" :: "l"(p));
}
static __device__ __forceinline__ uint32_t bfpack(float lo, float hi){
    uint32_t r; asm("cvt.rn.bf16x2.f32 %0, %1, %2;" : "=r"(r) : "f"(hi), "f"(lo)); return r;
}
static __device__ __forceinline__ void mma_bf16(float* d, uint32_t a0, uint32_t a1, uint32_t a2, uint32_t a3,
                                                uint32_t b0, uint32_t b1){
    asm volatile("mma.sync.aligned.m16n8k16.row.col.f32.bf16.bf16.f32 "
                 "{%0,%1,%2,%3}, {%4,%5,%6,%7}, {%8,%9}, {%0,%1,%2,%3};"
                 : "+f"(d[0]), "+f"(d[1]), "+f"(d[2]), "+f"(d[3])
                 : "r"(a0), "r"(a1), "r"(a2), "r"(a3), "r"(b0), "r"(b1));
}

static __device__ __forceinline__ void stage_x(float* sm, const float4* X4, int b0, int s, int buf, int tid){
    uint32_t base = (uint32_t)__cvta_generic_to_shared(sm + XOFF(buf));
    #pragma unroll
    for (int u = 0; u < BPB * 32 / NTHR; u++) {     // 8 per thread
        int v = tid + u * NTHR;
        int i = v >> 5, f = v & 31;
        uint32_t dst = base + (uint32_t)(i * XSTR + f * 4) * 4u;
        cp16(dst, X4 + ((size_t)(b0 + i) * MLEN + s) * 32 + f);
    }
    asm volatile("cp.async.commit_group;" ::: "memory");
}

// prefetch one position's tile (64 words x 512B) to L2: 1 line per thread
static __device__ __forceinline__ void pref_x(const float* X, int b0, int s, int tid){
    int i = tid >> 2, c = tid & 3;
    pref_l2(X + ((size_t)(b0 + i) * MLEN + s) * DDIM + c * 32);
}

__global__ __launch_bounds__(NTHR, 2)
void crf_main(const float* __restrict__ X, const void* __restrict__ Yv,
              const float* __restrict__ W, const float* __restrict__ T,
              float* __restrict__ out)
{
    extern __shared__ float sm[];
    const int tid  = threadIdx.x;
    const int wid  = tid >> 5;
    const int lane = tid & 31;
    const int g    = lane >> 2, t = lane & 3;
    const int wh   = wid & 3;          // row group
    const int kh   = wid >> 2;         // K half (0 or 1)
    const int b0   = blockIdx.x * BPB;
    const float4* X4 = (const float4*)X;

    stage_x(sm, X4, b0, 0, 0, tid);
    stage_x(sm, X4, b0, 1, 1, tid);
    pref_x(X, b0, 2, tid);
    pref_x(X, b0, 3, tid);

    // ---- prepack bf16 W fragments ----
    uint2* Bp = (uint2*)(sm + BPOFF);
    #pragma unroll
    for (int u = 0; u < 4; u++) {
        int i = tid + u * NTHR;
        int kt = i >> 7, rem = i & 127, nt = rem >> 5, ln = rem & 31;
        int n  = nt * 8 + (ln >> 2);
        int k0 = kt * 16 + (ln & 3) * 2;
        float w0 = 0.f, w1 = 0.f, w2 = 0.f, w3 = 0.f;
        if (n < LNUM) {
            w0 = W[n * DDIM + k0];     w1 = W[n * DDIM + k0 + 1];
            w2 = W[n * DDIM + k0 + 8]; w3 = W[n * DDIM + k0 + 9];
        }
        Bp[i] = make_uint2(bfpack(w0, w1), bfpack(w2, w3));
    }
    float* Tsm = sm + TSOFF;
    for (int i = tid; i < LNUM * LNUM; i += NTHR) Tsm[i] = T[i];
    if (tid == 0) {
        const int* y32 = (const int*)Yv;
        int nz = 0;
        for (int i = 1; i < 128; i += 2) nz |= y32[i];
        ((int*)sm)[FLGOFF] = (nz == 0) ? 1 : 0;
    }
    __syncthreads();

    // ---- preload Y labels ----
    {
        const bool is64i = ((int*)sm)[FLGOFF] != 0;
        int* Ys = (int*)sm + YSOFF;
        if (is64i) {
            const long long* Y64 = (const long long*)Yv;
            #pragma unroll
            for (int u = 0; u < BPB * MLEN / NTHR; u++) {
                int i = tid + u * NTHR;
                Ys[i] = (int)Y64[(size_t)b0 * MLEN + i];
            }
        } else {
            const int* Y32 = (const int*)Yv;
            #pragma unroll
            for (int u = 0; u < BPB * MLEN / NTHR; u++) {
                int i = tid + u * NTHR;
                Ys[i] = Y32[(size_t)b0 * MLEN + i];
            }
        }
    }

    // ---- expT B-fragments in registers (used by kh==0 warps) ----
    uint2 BT[2][4];
    #pragma unroll
    for (int kc = 0; kc < 2; kc++)
        #pragma unroll
        for (int nt = 0; nt < 4; nt++) {
            int j = nt * 8 + g;
            float v0 = 0.f, v1 = 0.f, v2 = 0.f, v3 = 0.f;
            if (j < LNUM) {
                int k0 = kc * 16 + 2 * t;
                if (k0     < LNUM) v0 = __expf(Tsm[(k0)     * LNUM + j]);
                if (k0 + 1 < LNUM) v1 = __expf(Tsm[(k0 + 1) * LNUM + j]);
                if (k0 + 8 < LNUM) v2 = __expf(Tsm[(k0 + 8) * LNUM + j]);
                if (k0 + 9 < LNUM) v3 = __expf(Tsm[(k0 + 9) * LNUM + j]);
            }
            BT[kc][nt] = make_uint2(bfpack(v0, v1), bfpack(v2, v3));
        }
    __syncthreads();

    const int* Ys = (int*)sm + YSOFF;
    float* Psm = sm + PSOFF + (wh * 32 + lane) * PSTR;

    const int wa = wh * 16 + g;
    const int wb = wa + 8;

    float a[4][4];
    #pragma unroll
    for (int nt = 0; nt < 4; nt++)
        #pragma unroll
        for (int r = 0; r < 4; r++) a[nt][r] = 1.0f;

    float node = 0.f, node8 = 0.f, edge = 0.f, edge8 = 0.f;
    float csc = 0.f, csc8 = 0.f, logz = 0.f, logz8 = 0.f;

    for (int s = 0; s < MLEN; s++) {
        const int buf = s & 1;

        // ---- L2 lookahead for the tile staged next step ----
        if (s + 3 < MLEN) pref_x(X, b0, s + 3, tid);

        if (s < MLEN - 1) asm volatile("cp.async.wait_group 1;" ::: "memory");
        else              asm volatile("cp.async.wait_group 0;" ::: "memory");
        __syncthreads();   // X(s) visible; Psm(s-1) consumed

        // ---- emission half-GEMM: rows [wh*16,+16) x N=32, K-half kh ----
        float e[4][4];
        #pragma unroll
        for (int nt = 0; nt < 4; nt++)
            #pragma unroll
            for (int r = 0; r < 4; r++) e[nt][r] = 0.f;
        {
            const float* Xb = sm + XOFF(buf) + (wh * 16) * XSTR;
            #pragma unroll
            for (int kl = 0; kl < 4; kl++) {
                const int kt = kh * 4 + kl;
                const float* xp = Xb + g * XSTR + kt * 16 + t * 2;
                float2 v0 = *(const float2*)(xp);
                float2 v2 = *(const float2*)(xp + 8);
                float2 v1 = *(const float2*)(xp + 8 * XSTR);
                float2 v3 = *(const float2*)(xp + 8 * XSTR + 8);
                uint32_t a0 = bfpack(v0.x, v0.y);
                uint32_t a1 = bfpack(v1.x, v1.y);
                uint32_t a2 = bfpack(v2.x, v2.y);
                uint32_t a3 = bfpack(v3.x, v3.y);
                const uint2* bp = Bp + kt * 128 + lane;
                uint2 bf0 = bp[0];
                uint2 bf1 = bp[32];
                uint2 bf2 = bp[64];
                uint2 bf3 = bp[96];
                mma_bf16(e[0], a0, a1, a2, a3, bf0.x, bf0.y);
                mma_bf16(e[1], a0, a1, a2, a3, bf1.x, bf1.y);
                mma_bf16(e[2], a0, a1, a2, a3, bf2.x, bf2.y);
                mma_bf16(e[3], a0, a1, a2, a3, bf3.x, bf3.y);
            }
        }
        if (kh == 1) {
            #pragma unroll
            for (int nt = 0; nt < 4; nt++)
                *(float4*)&Psm[nt * 4] = make_float4(e[nt][0], e[nt][1], e[nt][2], e[nt][3]);
        }
        __syncthreads();   // partials visible; X(buf) fully consumed

        if (s + 2 < MLEN) stage_x(sm, X4, b0, s + 2, buf, tid);

        if (kh == 0) {
            #pragma unroll
            for (int nt = 0; nt < 4; nt++) {
                float4 p = *(const float4*)&Psm[nt * 4];
                e[nt][0] += p.x; e[nt][1] += p.y; e[nt][2] += p.z; e[nt][3] += p.w;
            }

            int ya = Ys[wa * MLEN + s];
            int yb = Ys[wb * MLEN + s];
            #pragma unroll
            for (int nt = 0; nt < 4; nt++) {
                #pragma unroll
                for (int r = 0; r < 2; r++) {
                    int col = nt * 8 + 2 * t + r;
                    if (ya == col) node  += e[nt][r];
                    if (yb == col) node8 += e[nt][2 + r];
                }
            }

            float bt[4][4];
            #pragma unroll
            for (int nt = 0; nt < 4; nt++)
                #pragma unroll
                for (int r = 0; r < 4; r++) bt[nt][r] = a[nt][r] * __expf(e[nt][r]);

            if (s + 1 < MLEN) {
                if (t == 0) {
                    edge  += Tsm[ya * LNUM + Ys[wa * MLEN + s + 1]];
                    edge8 += Tsm[yb * LNUM + Ys[wb * MLEN + s + 1]];
                }
                float sv[4][4];
                #pragma unroll
                for (int nt = 0; nt < 4; nt++)
                    #pragma unroll
                    for (int r = 0; r < 4; r++) sv[nt][r] = 0.f;
                #pragma unroll
                for (int kc = 0; kc < 2; kc++) {
                    uint32_t a0 = bfpack(bt[2 * kc][0],     bt[2 * kc][1]);
                    uint32_t a1 = bfpack(bt[2 * kc][2],     bt[2 * kc][3]);
                    uint32_t a2 = bfpack(bt[2 * kc + 1][0], bt[2 * kc + 1][1]);
                    uint32_t a3 = bfpack(bt[2 * kc + 1][2], bt[2 * kc + 1][3]);
                    #pragma unroll
                    for (int nt = 0; nt < 4; nt++)
                        mma_bf16(sv[nt], a0, a1, a2, a3, BT[kc][nt].x, BT[kc][nt].y);
                }
                float mg = sv[0][0], m8 = sv[0][2];
                #pragma unroll
                for (int nt = 0; nt < 4; nt++) {
                    mg = fmaxf(mg, fmaxf(sv[nt][0], sv[nt][1]));
                    m8 = fmaxf(m8, fmaxf(sv[nt][2], sv[nt][3]));
                }
                mg = fmaxf(mg, __shfl_xor_sync(0xffffffffu, mg, 1));
                mg = fmaxf(mg, __shfl_xor_sync(0xffffffffu, mg, 2));
                m8 = fmaxf(m8, __shfl_xor_sync(0xffffffffu, m8, 1));
                m8 = fmaxf(m8, __shfl_xor_sync(0xffffffffu, m8, 2));
                float inv  = __fdividef(1.0f, mg);
                float inv8 = __fdividef(1.0f, m8);
                #pragma unroll
                for (int nt = 0; nt < 4; nt++) {
                    a[nt][0] = sv[nt][0] * inv;
                    a[nt][1] = sv[nt][1] * inv;
                    a[nt][2] = sv[nt][2] * inv8;
                    a[nt][3] = sv[nt][3] * inv8;
                }
                csc  += __logf(mg);
                csc8 += __logf(m8);
            } else {
                float ssum = 0.f, ssum8 = 0.f;
                #pragma unroll
                for (int nt = 0; nt < 4; nt++) {
                    ssum  += bt[nt][0] + bt[nt][1];
                    ssum8 += bt[nt][2] + bt[nt][3];
                }
                ssum  += __shfl_xor_sync(0xffffffffu, ssum, 1);
                ssum  += __shfl_xor_sync(0xffffffffu, ssum, 2);
                ssum8 += __shfl_xor_sync(0xffffffffu, ssum8, 1);
                ssum8 += __shfl_xor_sync(0xffffffffu, ssum8, 2);
                logz  = csc  + __logf(ssum);
                logz8 = csc8 + __logf(ssum8);
            }
        }
    }

    // ---- reduction (kh==0 warps hold values) ----
    float val = 0.f;
    if (kh == 0) {
        val = -(node + node8);
        if (t == 0) val += (logz - edge) + (logz8 - edge8);
    }
    #pragma unroll
    for (int o = 16; o; o >>= 1) val += __shfl_xor_sync(0xffffffffu, val, o);
    float* red = sm + REDOFF;
    if (wid < 4 && lane == 0) red[wid] = val;
    __syncthreads();

    __shared__ int s_last;
    if (tid == 0) {
        g_partials[blockIdx.x] = red[0] + red[1] + red[2] + red[3];
        __threadfence();
        unsigned int old = atomicAdd(&g_count, 1u);
        s_last = (old == (unsigned)(gridDim.x - 1)) ? 1 : 0;
    }
    __syncthreads();
    if (s_last && tid < 32) {
        __threadfence();
        const volatile float* gp = (const volatile float*)g_partials;
        float v = 0.f;
        #pragma unroll
        for (int i = 0; i < GRID / 32; i++) v += gp[lane + i * 32];  // fixed order
        #pragma unroll
        for (int o = 16; o; o >>= 1) v += __shfl_xor_sync(0xffffffffu, v, o);
        if (lane == 0) { out[0] = v; g_count = 0; }
    }
}

extern "C" void kernel_launch(void* const* d_in, const int* in_sizes, int n_in,
                              void* d_out, int out_size)
{
    const float* X = (const float*)d_in[0];
    const void*  Y = d_in[1];
    const float* W = (const float*)d_in[2];
    const float* T = (const float*)d_in[3];

    cudaFuncSetAttribute(crf_main, cudaFuncAttributeMaxDynamicSharedMemorySize, SMEM_BYTES);
    crf_main<<<GRID, NTHR, SMEM_BYTES>>>(X, Y, W, T, (float*)d_out);
}

// round 16
// speedup vs baseline: 1.0228x; 1.0228x over previous
#include <cuda_runtime.h>
#include <cstdint>

#define MLEN  16
#define DDIM  128
#define LNUM  26
#define BPB   64      // words per block
#define NTHR  256     // 8 warps: 4 row-groups x 2 K-halves
#define GRID  256
#define XSTR  136     // padded floats per X row
#define NBUF  2
#define PSTR  20      // floats per partial slot (bank-conflict-free)

// ---- smem layout (float indices) ----
#define XS_F    (BPB * XSTR)                 // 8704 per buffer
#define XOFF(b) ((b) * XS_F)
#define BPOFF   (NBUF * XS_F)                // 17408: Bp 1024 uint2 = 2048 floats
#define PSOFF   (BPOFF + 2048)               // 19456: partials 128 slots x 20 = 2560
#define TSOFF   (PSOFF + 128 * PSTR)         // 22016: raw T 676
#define YSOFF   (TSOFF + LNUM * LNUM)        // 22692: Y labels 64*16
#define REDOFF  (YSOFF + BPB * MLEN)         // 23716
#define FLGOFF  (REDOFF + 4)
#define SMEM_F  (FLGOFF + 4)
#define SMEM_BYTES (SMEM_F * 4)              // ~92.7 KB -> 2 blocks/SM (16 warps)

__device__ float g_partials[GRID];
__device__ unsigned int g_count;

static __device__ __forceinline__ void cp16(uint32_t dst, const void* src){
    asm volatile("cp.async.cg.shared.global [%0], [%1], 16;" :: "r"(dst), "l"(src));
}
static __device__ __forceinline__ void pref_l2(const void* p){
    asm volatile("prefetch.global.L2 [%0];" :: "l"(p));
}
static __device__ __forceinline__ uint32_t bfpack(float lo, float hi){
    uint32_t r; asm("cvt.rn.bf16x2.f32 %0, %1, %2;" : "=r"(r) : "f"(hi), "f"(lo)); return r;
}
static __device__ __forceinline__ void mma_bf16(float* d, uint32_t a0, uint32_t a1, uint32_t a2, uint32_t a3,
                                                uint32_t b0, uint32_t b1){
    asm volatile("mma.sync.aligned.m16n8k16.row.col.f32.bf16.bf16.f32 "
                 "{%0,%1,%2,%3}, {%4,%5,%6,%7}, {%8,%9}, {%0,%1,%2,%3};"
                 : "+f"(d[0]), "+f"(d[1]), "+f"(d[2]), "+f"(d[3])
                 : "r"(a0), "r"(a1), "r"(a2), "r"(a3), "r"(b0), "r"(b1));
}

static __device__ __forceinline__ void stage_x(float* sm, const float4* X4, int b0, int s, int buf, int tid){
    uint32_t base = (uint32_t)__cvta_generic_to_shared(sm + XOFF(buf));
    #pragma unroll
    for (int u = 0; u < BPB * 32 / NTHR; u++) {     // 8 per thread
        int v = tid + u * NTHR;
        int i = v >> 5, f = v & 31;
        uint32_t dst = base + (uint32_t)(i * XSTR + f * 4) * 4u;
        cp16(dst, X4 + ((size_t)(b0 + i) * MLEN + s) * 32 + f);
    }
    asm volatile("cp.async.commit_group;" ::: "memory");
}

// prefetch one position's tile (64 words x 512B) to L2: 1 line per thread
static __device__ __forceinline__ void pref_x(const float* X, int b0, int s, int tid){
    int i = tid >> 2, c = tid & 3;
    pref_l2(X + ((size_t)(b0 + i) * MLEN + s) * DDIM + c * 32);
}

__global__ __launch_bounds__(NTHR, 2)
void crf_main(const float* __restrict__ X, const void* __restrict__ Yv,
              const float* __restrict__ W, const float* __restrict__ T,
              float* __restrict__ out)
{
    extern __shared__ float sm[];
    const int tid  = threadIdx.x;
    const int wid  = tid >> 5;
    const int lane = tid & 31;
    const int g    = lane >> 2, t = lane & 3;
    const int wh   = wid & 3;          // row group
    const int kh   = wid >> 2;         // K half (0 or 1)
    const int b0   = blockIdx.x * BPB;
    const float4* X4 = (const float4*)X;

    stage_x(sm, X4, b0, 0, 0, tid);
    stage_x(sm, X4, b0, 1, 1, tid);
    pref_x(X, b0, 2, tid);
    pref_x(X, b0, 3, tid);

    // ---- prepack bf16 W fragments ----
    uint2* Bp = (uint2*)(sm + BPOFF);
    #pragma unroll
    for (int u = 0; u < 4; u++) {
        int i = tid + u * NTHR;
        int kt = i >> 7, rem = i & 127, nt = rem >> 5, ln = rem & 31;
        int n  = nt * 8 + (ln >> 2);
        int k0 = kt * 16 + (ln & 3) * 2;
        float w0 = 0.f, w1 = 0.f, w2 = 0.f, w3 = 0.f;
        if (n < LNUM) {
            w0 = W[n * DDIM + k0];     w1 = W[n * DDIM + k0 + 1];
            w2 = W[n * DDIM + k0 + 8]; w3 = W[n * DDIM + k0 + 9];
        }
        Bp[i] = make_uint2(bfpack(w0, w1), bfpack(w2, w3));
    }
    float* Tsm = sm + TSOFF;
    for (int i = tid; i < LNUM * LNUM; i += NTHR) Tsm[i] = T[i];
    if (tid == 0) {
        const int* y32 = (const int*)Yv;
        int nz = 0;
        for (int i = 1; i < 128; i += 2) nz |= y32[i];
        ((int*)sm)[FLGOFF] = (nz == 0) ? 1 : 0;
    }
    __syncthreads();

    // ---- preload Y labels ----
    {
        const bool is64i = ((int*)sm)[FLGOFF] != 0;
        int* Ys = (int*)sm + YSOFF;
        if (is64i) {
            const long long* Y64 = (const long long*)Yv;
            #pragma unroll
            for (int u = 0; u < BPB * MLEN / NTHR; u++) {
                int i = tid + u * NTHR;
                Ys[i] = (int)Y64[(size_t)b0 * MLEN + i];
            }
        } else {
            const int* Y32 = (const int*)Yv;
            #pragma unroll
            for (int u = 0; u < BPB * MLEN / NTHR; u++) {
                int i = tid + u * NTHR;
                Ys[i] = Y32[(size_t)b0 * MLEN + i];
            }
        }
    }

    // ---- expT B-fragments in registers (used by kh==0 warps) ----
    uint2 BT[2][4];
    #pragma unroll
    for (int kc = 0; kc < 2; kc++)
        #pragma unroll
        for (int nt = 0; nt < 4; nt++) {
            int j = nt * 8 + g;
            float v0 = 0.f, v1 = 0.f, v2 = 0.f, v3 = 0.f;
            if (j < LNUM) {
                int k0 = kc * 16 + 2 * t;
                if (k0     < LNUM) v0 = __expf(Tsm[(k0)     * LNUM + j]);
                if (k0 + 1 < LNUM) v1 = __expf(Tsm[(k0 + 1) * LNUM + j]);
                if (k0 + 8 < LNUM) v2 = __expf(Tsm[(k0 + 8) * LNUM + j]);
                if (k0 + 9 < LNUM) v3 = __expf(Tsm[(k0 + 9) * LNUM + j]);
            }
            BT[kc][nt] = make_uint2(bfpack(v0, v1), bfpack(v2, v3));
        }
    __syncthreads();

    const int* Ys = (int*)sm + YSOFF;
    float* Psm = sm + PSOFF + (wh * 32 + lane) * PSTR;

    const int wa = wh * 16 + g;
    const int wb = wa + 8;

    float a[4][4];
    #pragma unroll
    for (int nt = 0; nt < 4; nt++)
        #pragma unroll
        for (int r = 0; r < 4; r++) a[nt][r] = 1.0f;

    float node = 0.f, node8 = 0.f, edge = 0.f, edge8 = 0.f;
    float csc = 0.f, csc8 = 0.f, logz = 0.f, logz8 = 0.f;

    for (int s = 0; s < MLEN; s++) {
        const int buf = s & 1;

        // ---- L2 lookahead for the tile staged next step ----
        if (s + 3 < MLEN) pref_x(X, b0, s + 3, tid);

        if (s < MLEN - 1) asm volatile("cp.async.wait_group 1;" ::: "memory");
        else              asm volatile("cp.async.wait_group 0;" ::: "memory");
        __syncthreads();   // X(s) visible; Psm(s-1) consumed

        // ---- emission half-GEMM: rows [wh*16,+16) x N=32, K-half kh ----
        float e[4][4];
        #pragma unroll
        for (int nt = 0; nt < 4; nt++)
            #pragma unroll
            for (int r = 0; r < 4; r++) e[nt][r] = 0.f;
        {
            const float* Xb = sm + XOFF(buf) + (wh * 16) * XSTR;
            #pragma unroll
            for (int kl = 0; kl < 4; kl++) {
                const int kt = kh * 4 + kl;
                const float* xp = Xb + g * XSTR + kt * 16 + t * 2;
                float2 v0 = *(const float2*)(xp);
                float2 v2 = *(const float2*)(xp + 8);
                float2 v1 = *(const float2*)(xp + 8 * XSTR);
                float2 v3 = *(const float2*)(xp + 8 * XSTR + 8);
                uint32_t a0 = bfpack(v0.x, v0.y);
                uint32_t a1 = bfpack(v1.x, v1.y);
                uint32_t a2 = bfpack(v2.x, v2.y);
                uint32_t a3 = bfpack(v3.x, v3.y);
                const uint2* bp = Bp + kt * 128 + lane;
                uint2 bf0 = bp[0];
                uint2 bf1 = bp[32];
                uint2 bf2 = bp[64];
                uint2 bf3 = bp[96];
                mma_bf16(e[0], a0, a1, a2, a3, bf0.x, bf0.y);
                mma_bf16(e[1], a0, a1, a2, a3, bf1.x, bf1.y);
                mma_bf16(e[2], a0, a1, a2, a3, bf2.x, bf2.y);
                mma_bf16(e[3], a0, a1, a2, a3, bf3.x, bf3.y);
            }
        }
        if (kh == 1) {
            #pragma unroll
            for (int nt = 0; nt < 4; nt++)
                *(float4*)&Psm[nt * 4] = make_float4(e[nt][0], e[nt][1], e[nt][2], e[nt][3]);
        }
        __syncthreads();   // partials visible; X(buf) fully consumed

        if (s + 2 < MLEN) stage_x(sm, X4, b0, s + 2, buf, tid);

        if (kh == 0) {
            #pragma unroll
            for (int nt = 0; nt < 4; nt++) {
                float4 p = *(const float4*)&Psm[nt * 4];
                e[nt][0] += p.x; e[nt][1] += p.y; e[nt][2] += p.z; e[nt][3] += p.w;
            }

            int ya = Ys[wa * MLEN + s];
            int yb = Ys[wb * MLEN + s];
            #pragma unroll
            for (int nt = 0; nt < 4; nt++) {
                #pragma unroll
                for (int r = 0; r < 2; r++) {
                    int col = nt * 8 + 2 * t + r;
                    if (ya == col) node  += e[nt][r];
                    if (yb == col) node8 += e[nt][2 + r];
                }
            }

            float bt[4][4];
            #pragma unroll
            for (int nt = 0; nt < 4; nt++)
                #pragma unroll
                for (int r = 0; r < 4; r++) bt[nt][r] = a[nt][r] * __expf(e[nt][r]);

            if (s + 1 < MLEN) {
                if (t == 0) {
                    edge  += Tsm[ya * LNUM + Ys[wa * MLEN + s + 1]];
                    edge8 += Tsm[yb * LNUM + Ys[wb * MLEN + s + 1]];
                }
                float sv[4][4];
                #pragma unroll
                for (int nt = 0; nt < 4; nt++)
                    #pragma unroll
                    for (int r = 0; r < 4; r++) sv[nt][r] = 0.f;
                #pragma unroll
                for (int kc = 0; kc < 2; kc++) {
                    uint32_t a0 = bfpack(bt[2 * kc][0],     bt[2 * kc][1]);
                    uint32_t a1 = bfpack(bt[2 * kc][2],     bt[2 * kc][3]);
                    uint32_t a2 = bfpack(bt[2 * kc + 1][0], bt[2 * kc + 1][1]);
                    uint32_t a3 = bfpack(bt[2 * kc + 1][2], bt[2 * kc + 1][3]);
                    #pragma unroll
                    for (int nt = 0; nt < 4; nt++)
                        mma_bf16(sv[nt], a0, a1, a2, a3, BT[kc][nt].x, BT[kc][nt].y);
                }
                float mg = sv[0][0], m8 = sv[0][2];
                #pragma unroll
                for (int nt = 0; nt < 4; nt++) {
                    mg = fmaxf(mg, fmaxf(sv[nt][0], sv[nt][1]));
                    m8 = fmaxf(m8, fmaxf(sv[nt][2], sv[nt][3]));
                }
                mg = fmaxf(mg, __shfl_xor_sync(0xffffffffu, mg, 1));
                mg = fmaxf(mg, __shfl_xor_sync(0xffffffffu, mg, 2));
                m8 = fmaxf(m8, __shfl_xor_sync(0xffffffffu, m8, 1));
                m8 = fmaxf(m8, __shfl_xor_sync(0xffffffffu, m8, 2));
                float inv  = __fdividef(1.0f, mg);
                float inv8 = __fdividef(1.0f, m8);
                #pragma unroll
                for (int nt = 0; nt < 4; nt++) {
                    a[nt][0] = sv[nt][0] * inv;
                    a[nt][1] = sv[nt][1] * inv;
                    a[nt][2] = sv[nt][2] * inv8;
                    a[nt][3] = sv[nt][3] * inv8;
                }
                csc  += __logf(mg);
                csc8 += __logf(m8);
            } else {
                float ssum = 0.f, ssum8 = 0.f;
                #pragma unroll
                for (int nt = 0; nt < 4; nt++) {
                    ssum  += bt[nt][0] + bt[nt][1];
                    ssum8 += bt[nt][2] + bt[nt][3];
                }
                ssum  += __shfl_xor_sync(0xffffffffu, ssum, 1);
                ssum  += __shfl_xor_sync(0xffffffffu, ssum, 2);
                ssum8 += __shfl_xor_sync(0xffffffffu, ssum8, 1);
                ssum8 += __shfl_xor_sync(0xffffffffu, ssum8, 2);
                logz  = csc  + __logf(ssum);
                logz8 = csc8 + __logf(ssum8);
            }
        }
    }

    // ---- reduction (kh==0 warps hold values) ----
    float val = 0.f;
    if (kh == 0) {
        val = -(node + node8);
        if (t == 0) val += (logz - edge) + (logz8 - edge8);
    }
    #pragma unroll
    for (int o = 16; o; o >>= 1) val += __shfl_xor_sync(0xffffffffu, val, o);
    float* red = sm + REDOFF;
    if (wid < 4 && lane == 0) red[wid] = val;
    __syncthreads();

    __shared__ int s_last;
    if (tid == 0) {
        g_partials[blockIdx.x] = red[0] + red[1] + red[2] + red[3];
        __threadfence();
        unsigned int old = atomicAdd(&g_count, 1u);
        s_last = (old == (unsigned)(gridDim.x - 1)) ? 1 : 0;
    }
    __syncthreads();
    if (s_last && tid < 32) {
        __threadfence();
        const volatile float* gp = (const volatile float*)g_partials;
        float v = 0.f;
        #pragma unroll
        for (int i = 0; i < GRID / 32; i++) v += gp[lane + i * 32];  // fixed order
        #pragma unroll
        for (int o = 16; o; o >>= 1) v += __shfl_xor_sync(0xffffffffu, v, o);
        if (lane == 0) { out[0] = v; g_count = 0; }
    }
}

extern "C" void kernel_launch(void* const* d_in, const int* in_sizes, int n_in,
                              void* d_out, int out_size)
{
    const float* X = (const float*)d_in[0];
    const void*  Y = d_in[1];
    const float* W = (const float*)d_in[2];
    const float* T = (const float*)d_in[3];

    cudaFuncSetAttribute(crf_main, cudaFuncAttributeMaxDynamicSharedMemorySize, SMEM_BYTES);
    crf_main<<<GRID, NTHR, SMEM_BYTES>>>(X, Y, W, T, (float*)d_out);
}

// round 17
// speedup vs baseline: 1.3273x; 1.2977x over previous
#include <cuda_runtime.h>
#include <cstdint>

#define MLEN  16
#define DDIM  128
#define LNUM  26
#define BPB   64      // words per block
#define NTHR  256     // 8 warps: 4 row-groups x 2 K-halves
#define GRID  256
#define XSTR  136     // padded floats per X row
#define NBUF  2
#define PSTR  20      // floats per partial slot

// ---- smem layout (float indices) ----
#define XS_F    (BPB * XSTR)                 // 8704 per buffer
#define XOFF(b) ((b) * XS_F)
#define BPOFF   (NBUF * XS_F)                // 17408: Bp 1024 uint2 = 2048 floats
#define PSOFF   (BPOFF + 2048)               // 19456: partials 2 bufs x 128 x 20 = 5120
#define TSOFF   (PSOFF + 2 * 128 * PSTR)     // 24576: raw T 676
#define YSOFF   (TSOFF + LNUM * LNUM)        // 25252: Y labels 64*16
#define REDOFF  (YSOFF + BPB * MLEN)         // 26276
#define FLGOFF  (REDOFF + 4)
#define SMEM_F  (FLGOFF + 4)
#define SMEM_BYTES (SMEM_F * 4)              // ~105 KB -> 2 blocks/SM

__device__ float g_partials[GRID];
__device__ unsigned int g_count;

static __device__ __forceinline__ void cp16(uint32_t dst, const void* src){
    asm volatile("cp.async.cg.shared.global [%0], [%1], 16;" :: "r"(dst), "l"(src));
}
static __device__ __forceinline__ uint32_t bfpack(float lo, float hi){
    uint32_t r; asm("cvt.rn.bf16x2.f32 %0, %1, %2;" : "=r"(r) : "f"(hi), "f"(lo)); return r;
}
static __device__ __forceinline__ void mma_bf16(float* d, uint32_t a0, uint32_t a1, uint32_t a2, uint32_t a3,
                                                uint32_t b0, uint32_t b1){
    asm volatile("mma.sync.aligned.m16n8k16.row.col.f32.bf16.bf16.f32 "
                 "{%0,%1,%2,%3}, {%4,%5,%6,%7}, {%8,%9}, {%0,%1,%2,%3};"
                 : "+f"(d[0]), "+f"(d[1]), "+f"(d[2]), "+f"(d[3])
                 : "r"(a0), "r"(a1), "r"(a2), "r"(a3), "r"(b0), "r"(b1));
}
static __device__ __forceinline__ void pair_bar(int wh){
    asm volatile("bar.sync %0, 64;" :: "r"(1 + wh) : "memory");
}

// stage THIS WARP's region of position s: rows [wh*16,+16), float4 cols [kh*16,+16)
static __device__ __forceinline__ void stage_own(float* sm, const float4* X4, int b0, int s, int buf,
                                                 int wh, int kh, int lane){
    uint32_t base = (uint32_t)__cvta_generic_to_shared(sm + XOFF(buf));
    #pragma unroll
    for (int u = 0; u < 8; u++) {
        int v = lane + u * 32;                  // 0..255
        int il = v >> 4, fl = v & 15;
        int i = wh * 16 + il;
        int f = kh * 16 + fl;
        uint32_t dst = base + (uint32_t)(i * XSTR + f * 4) * 4u;
        cp16(dst, X4 + ((size_t)(b0 + i) * MLEN + s) * 32 + f);
    }
    asm volatile("cp.async.commit_group;" ::: "memory");
}

__global__ __launch_bounds__(NTHR, 2)
void crf_main(const float* __restrict__ X, const void* __restrict__ Yv,
              const float* __restrict__ W, const float* __restrict__ T,
              float* __restrict__ out)
{
    extern __shared__ float sm[];
    const int tid  = threadIdx.x;
    const int wid  = tid >> 5;
    const int lane = tid & 31;
    const int g    = lane >> 2, t = lane & 3;
    const int wh   = wid & 3;          // row group / pair id
    const int kh   = wid >> 2;         // K half (0 or 1)
    const int b0   = blockIdx.x * BPB;
    const float4* X4 = (const float4*)X;

    // prologue: each warp stages its own regions of positions 0 and 1
    stage_own(sm, X4, b0, 0, 0, wh, kh, lane);
    stage_own(sm, X4, b0, 1, 1, wh, kh, lane);

    // ---- prepack bf16 W fragments ----
    uint2* Bp = (uint2*)(sm + BPOFF);
    #pragma unroll
    for (int u = 0; u < 4; u++) {
        int i = tid + u * NTHR;
        int kt = i >> 7, rem = i & 127, nt = rem >> 5, ln = rem & 31;
        int n  = nt * 8 + (ln >> 2);
        int k0 = kt * 16 + (ln & 3) * 2;
        float w0 = 0.f, w1 = 0.f, w2 = 0.f, w3 = 0.f;
        if (n < LNUM) {
            w0 = W[n * DDIM + k0];     w1 = W[n * DDIM + k0 + 1];
            w2 = W[n * DDIM + k0 + 8]; w3 = W[n * DDIM + k0 + 9];
        }
        Bp[i] = make_uint2(bfpack(w0, w1), bfpack(w2, w3));
    }
    float* Tsm = sm + TSOFF;
    for (int i = tid; i < LNUM * LNUM; i += NTHR) Tsm[i] = T[i];
    if (tid == 0) {
        const int* y32 = (const int*)Yv;
        int nz = 0;
        for (int i = 1; i < 128; i += 2) nz |= y32[i];
        ((int*)sm)[FLGOFF] = (nz == 0) ? 1 : 0;
    }
    __syncthreads();

    // ---- preload Y labels ----
    {
        const bool is64i = ((int*)sm)[FLGOFF] != 0;
        int* Ys = (int*)sm + YSOFF;
        if (is64i) {
            const long long* Y64 = (const long long*)Yv;
            #pragma unroll
            for (int u = 0; u < BPB * MLEN / NTHR; u++) {
                int i = tid + u * NTHR;
                Ys[i] = (int)Y64[(size_t)b0 * MLEN + i];
            }
        } else {
            const int* Y32 = (const int*)Yv;
            #pragma unroll
            for (int u = 0; u < BPB * MLEN / NTHR; u++) {
                int i = tid + u * NTHR;
                Ys[i] = Y32[(size_t)b0 * MLEN + i];
            }
        }
    }

    // ---- expT B-fragments in registers (used by kh==0 warps) ----
    uint2 BT[2][4];
    #pragma unroll
    for (int kc = 0; kc < 2; kc++)
        #pragma unroll
        for (int nt = 0; nt < 4; nt++) {
            int j = nt * 8 + g;
            float v0 = 0.f, v1 = 0.f, v2 = 0.f, v3 = 0.f;
            if (j < LNUM) {
                int k0 = kc * 16 + 2 * t;
                if (k0     < LNUM) v0 = __expf(Tsm[(k0)     * LNUM + j]);
                if (k0 + 1 < LNUM) v1 = __expf(Tsm[(k0 + 1) * LNUM + j]);
                if (k0 + 8 < LNUM) v2 = __expf(Tsm[(k0 + 8) * LNUM + j]);
                if (k0 + 9 < LNUM) v3 = __expf(Tsm[(k0 + 9) * LNUM + j]);
            }
            BT[kc][nt] = make_uint2(bfpack(v0, v1), bfpack(v2, v3));
        }
    __syncthreads();   // init done; from here, pairs free-run

    const int* Ys = (int*)sm + YSOFF;

    const int wa = wh * 16 + g;
    const int wb = wa + 8;

    float a[4][4];
    #pragma unroll
    for (int nt = 0; nt < 4; nt++)
        #pragma unroll
        for (int r = 0; r < 4; r++) a[nt][r] = 1.0f;

    float node = 0.f, node8 = 0.f, edge = 0.f, edge8 = 0.f;
    float csc = 0.f, csc8 = 0.f, logz = 0.f, logz8 = 0.f;

    for (int s = 0; s < MLEN; s++) {
        const int buf = s & 1;
        float* Psm = sm + PSOFF + (s & 1) * 128 * PSTR + (wh * 32 + lane) * PSTR;

        // ---- own region of X(s) landed? (per-thread wait + warp sync) ----
        if (s < MLEN - 1) asm volatile("cp.async.wait_group 1;" ::: "memory");
        else              asm volatile("cp.async.wait_group 0;" ::: "memory");
        __syncwarp();

        // ---- emission half-GEMM: rows [wh*16,+16) x N=32, K-half kh ----
        float e[4][4];
        #pragma unroll
        for (int nt = 0; nt < 4; nt++)
            #pragma unroll
            for (int r = 0; r < 4; r++) e[nt][r] = 0.f;
        {
            const float* Xb = sm + XOFF(buf) + (wh * 16) * XSTR;
            #pragma unroll
            for (int kl = 0; kl < 4; kl++) {
                const int kt = kh * 4 + kl;
                const float* xp = Xb + g * XSTR + kt * 16 + t * 2;
                float2 v0 = *(const float2*)(xp);
                float2 v2 = *(const float2*)(xp + 8);
                float2 v1 = *(const float2*)(xp + 8 * XSTR);
                float2 v3 = *(const float2*)(xp + 8 * XSTR + 8);
                uint32_t a0 = bfpack(v0.x, v0.y);
                uint32_t a1 = bfpack(v1.x, v1.y);
                uint32_t a2 = bfpack(v2.x, v2.y);
                uint32_t a3 = bfpack(v3.x, v3.y);
                const uint2* bp = Bp + kt * 128 + lane;
                uint2 bf0 = bp[0];
                uint2 bf1 = bp[32];
                uint2 bf2 = bp[64];
                uint2 bf3 = bp[96];
                mma_bf16(e[0], a0, a1, a2, a3, bf0.x, bf0.y);
                mma_bf16(e[1], a0, a1, a2, a3, bf1.x, bf1.y);
                mma_bf16(e[2], a0, a1, a2, a3, bf2.x, bf2.y);
                mma_bf16(e[3], a0, a1, a2, a3, bf3.x, bf3.y);
            }
        }
        if (kh == 1) {
            #pragma unroll
            for (int nt = 0; nt < 4; nt++)
                *(float4*)&Psm[nt * 4] = make_float4(e[nt][0], e[nt][1], e[nt][2], e[nt][3]);
        }

        // ---- pair rendezvous: partials(s) visible to kh==0 ----
        pair_bar(wh);

        if (kh == 0) {
            #pragma unroll
            for (int nt = 0; nt < 4; nt++) {
                float4 p = *(const float4*)&Psm[nt * 4];
                e[nt][0] += p.x; e[nt][1] += p.y; e[nt][2] += p.z; e[nt][3] += p.w;
            }

            int ya = Ys[wa * MLEN + s];
            int yb = Ys[wb * MLEN + s];
            #pragma unroll
            for (int nt = 0; nt < 4; nt++) {
                #pragma unroll
                for (int r = 0; r < 2; r++) {
                    int col = nt * 8 + 2 * t + r;
                    if (ya == col) node  += e[nt][r];
                    if (yb == col) node8 += e[nt][2 + r];
                }
            }

            float bt[4][4];
            #pragma unroll
            for (int nt = 0; nt < 4; nt++)
                #pragma unroll
                for (int r = 0; r < 4; r++) bt[nt][r] = a[nt][r] * __expf(e[nt][r]);

            if (s + 1 < MLEN) {
                if (t == 0) {
                    edge  += Tsm[ya * LNUM + Ys[wa * MLEN + s + 1]];
                    edge8 += Tsm[yb * LNUM + Ys[wb * MLEN + s + 1]];
                }
                float sv[4][4];
                #pragma unroll
                for (int nt = 0; nt < 4; nt++)
                    #pragma unroll
                    for (int r = 0; r < 4; r++) sv[nt][r] = 0.f;
                #pragma unroll
                for (int kc = 0; kc < 2; kc++) {
                    uint32_t a0 = bfpack(bt[2 * kc][0],     bt[2 * kc][1]);
                    uint32_t a1 = bfpack(bt[2 * kc][2],     bt[2 * kc][3]);
                    uint32_t a2 = bfpack(bt[2 * kc + 1][0], bt[2 * kc + 1][1]);
                    uint32_t a3 = bfpack(bt[2 * kc + 1][2], bt[2 * kc + 1][3]);
                    #pragma unroll
                    for (int nt = 0; nt < 4; nt++)
                        mma_bf16(sv[nt], a0, a1, a2, a3, BT[kc][nt].x, BT[kc][nt].y);
                }
                float mg = sv[0][0], m8 = sv[0][2];
                #pragma unroll
                for (int nt = 0; nt < 4; nt++) {
                    mg = fmaxf(mg, fmaxf(sv[nt][0], sv[nt][1]));
                    m8 = fmaxf(m8, fmaxf(sv[nt][2], sv[nt][3]));
                }
                mg = fmaxf(mg, __shfl_xor_sync(0xffffffffu, mg, 1));
                mg = fmaxf(mg, __shfl_xor_sync(0xffffffffu, mg, 2));
                m8 = fmaxf(m8, __shfl_xor_sync(0xffffffffu, m8, 1));
                m8 = fmaxf(m8, __shfl_xor_sync(0xffffffffu, m8, 2));
                float inv  = __fdividef(1.0f, mg);
                float inv8 = __fdividef(1.0f, m8);
                #pragma unroll
                for (int nt = 0; nt < 4; nt++) {
                    a[nt][0] = sv[nt][0] * inv;
                    a[nt][1] = sv[nt][1] * inv;
                    a[nt][2] = sv[nt][2] * inv8;
                    a[nt][3] = sv[nt][3] * inv8;
                }
                csc  += __logf(mg);
                csc8 += __logf(m8);
            } else {
                float ssum = 0.f, ssum8 = 0.f;
                #pragma unroll
                for (int nt = 0; nt < 4; nt++) {
                    ssum  += bt[nt][0] + bt[nt][1];
                    ssum8 += bt[nt][2] + bt[nt][3];
                }
                ssum  += __shfl_xor_sync(0xffffffffu, ssum, 1);
                ssum  += __shfl_xor_sync(0xffffffffu, ssum, 2);
                ssum8 += __shfl_xor_sync(0xffffffffu, ssum8, 1);
                ssum8 += __shfl_xor_sync(0xffffffffu, ssum8, 2);
                logz  = csc  + __logf(ssum);
                logz8 = csc8 + __logf(ssum8);
            }
        }

        // ---- refill own region (own GEMM reads of buf are done; nobody else reads it) ----
        if (s + 2 < MLEN) stage_own(sm, X4, b0, s + 2, buf, wh, kh, lane);
    }

    // ---- reduction (kh==0 warps: wid 0..3) ----
    float val = 0.f;
    if (kh == 0) {
        val = -(node + node8);
        if (t == 0) val += (logz - edge) + (logz8 - edge8);
    }
    #pragma unroll
    for (int o = 16; o; o >>= 1) val += __shfl_xor_sync(0xffffffffu, val, o);
    float* red = sm + REDOFF;
    if (wid < 4 && lane == 0) red[wid] = val;
    __syncthreads();

    __shared__ int s_last;
    if (tid == 0) {
        g_partials[blockIdx.x] = red[0] + red[1] + red[2] + red[3];
        __threadfence();
        unsigned int old = atomicAdd(&g_count, 1u);
        s_last = (old == (unsigned)(gridDim.x - 1)) ? 1 : 0;
    }
    __syncthreads();
    if (s_last && tid < 32) {
        __threadfence();
        const volatile float* gp = (const volatile float*)g_partials;
        float v = 0.f;
        #pragma unroll
        for (int i = 0; i < GRID / 32; i++) v += gp[lane + i * 32];  // fixed order
        #pragma unroll
        for (int o = 16; o; o >>= 1) v += __shfl_xor_sync(0xffffffffu, v, o);
        if (lane == 0) { out[0] = v; g_count = 0; }
    }
}

extern "C" void kernel_launch(void* const* d_in, const int* in_sizes, int n_in,
                              void* d_out, int out_size)
{
    const float* X = (const float*)d_in[0];
    const void*  Y = d_in[1];
    const float* W = (const float*)d_in[2];
    const float* T = (const float*)d_in[3];

    cudaFuncSetAttribute(crf_main, cudaFuncAttributeMaxDynamicSharedMemorySize, SMEM_BYTES);
    crf_main<<<GRID, NTHR, SMEM_BYTES>>>(X, Y, W, T, (float*)d_out);
}